// round 14
// baseline (speedup 1.0000x reference)
#include <cuda_runtime.h>
#include <cuda_fp16.h>
#include <math.h>
#include <cstdint>

// B=128, N=NONGT=36, D=1024, H=16, DG=64, PE=64
#define GM 4608      // rows = B*N
#define GN 3072      // cols = 3*1024  [q|k|vproj]
#define GK 1024      // inner dim
#define KP 1024      // fp16 K (single term Ah @ Bh)
#define BM 128
#define BN 128
#define BK 64
#define NK (KP / BK)   // 16
#define STG 32768      // stage stride: A 16KB + B 16KB
#define NSTAGE 3
#define CHUNK_ROWS 1152   // 9 block-rows = 32 batches per chunk

// ---------------- device scratch ----------------
__device__ __align__(16) __half g_Ah[(size_t)GM * KP];    // 9.4 MB
__device__ __align__(16) __half g_Bh[(size_t)GN * KP];    // 6.3 MB  [N,K] K-major
__device__ __align__(16) float g_bcat[GN];
__device__ __align__(16) __half g_qkvh[(size_t)GM * GN];  // 28.3 MB fp16 [q|k|vproj]
__device__ __align__(16) float g_pre[4608 * 16 * 36];     // 10.6 MB pre[b,n][h][m]

// ---------------- helpers ----------------
__device__ __forceinline__ uint32_t smem_u32(const void* p) {
    uint32_t a;
    asm("{ .reg .u64 t; cvta.to.shared.u64 t, %1; cvt.u32.u64 %0, t; }" : "=r"(a) : "l"(p));
    return a;
}
__device__ __forceinline__ void cp16(uint32_t d, const void* s) {
    asm volatile("cp.async.cg.shared.global [%0], [%1], 16;" :: "r"(d), "l"(s));
}

// ---------------- K0a: A fp32 -> fp16 ----------------
__global__ __launch_bounds__(256) void conv_A(const float* __restrict__ A) {
    int i = blockIdx.x * 256 + threadIdx.x;
    float4 v = ((const float4*)A)[i];
    __half2 h01 = __halves2half2(__float2half_rn(v.x), __float2half_rn(v.y));
    __half2 h23 = __halves2half2(__float2half_rn(v.z), __float2half_rn(v.w));
    size_t base = (size_t)i * 4;
    *(__half2*)&g_Ah[base] = h01; *(__half2*)&g_Ah[base + 2] = h23;
}

// ---------------- K0b: weights -> fp16 ----------------
__global__ __launch_bounds__(256) void conv_B(const float* __restrict__ Wq,
                                              const float* __restrict__ Wk,
                                              const float* __restrict__ Wout) {
    int i = blockIdx.x * 256 + threadIdx.x;
    int row = i >> 8;
    int c4 = (i & 255) << 2;
    const float* src = (row < 1024) ? (Wq + (size_t)row * 1024)
                     : (row < 2048) ? (Wk + (size_t)(row - 1024) * 1024)
                                    : (Wout + (size_t)(row - 2048) * 1024);
    float4 v = *(const float4*)(src + c4);
    __half2 h01 = __halves2half2(__float2half_rn(v.x), __float2half_rn(v.y));
    __half2 h23 = __halves2half2(__float2half_rn(v.z), __float2half_rn(v.w));
    size_t base = (size_t)row * KP + c4;
    *(__half2*)&g_Bh[base] = h01; *(__half2*)&g_Bh[base + 2] = h23;
}

__global__ void fill_bcat(const float* __restrict__ bq, const float* __restrict__ bk) {
    int n = blockIdx.x * 256 + threadIdx.x;
    float v = 0.f;
    if (n < 1024) v = bq[n];
    else if (n < 2048) v = bk[n - 1024];
    g_bcat[n] = v;
}

// ---------------- K1: HMMA GEMM chunk  qkv[bm_off..] = A @ B^T + bcat ----------------
__device__ __forceinline__ void load_tile(uint32_t base, const __half* Ag, const __half* Bg, int t) {
#pragma unroll
    for (int i = 0; i < 4; i++) {
        int u = t + i * 256;
        int row = u >> 3, k = u & 7;
        uint32_t sw = row * 128 + ((k ^ (row & 7)) << 4);
        cp16(base + sw, (const char*)(Ag + (size_t)row * KP) + k * 16);
        cp16(base + 16384 + sw, (const char*)(Bg + (size_t)row * KP) + k * 16);
    }
    asm volatile("cp.async.commit_group;" ::: "memory");
}

__global__ __launch_bounds__(256, 2) void gemm_hmma(int bm_off) {
    extern __shared__ char smem[];
    uint32_t sb = smem_u32(smem);
    int t = threadIdx.x, lane = t & 31, wid = t >> 5;
    int bm = bm_off + blockIdx.y * BM, bn = blockIdx.x * BN;
    int wm = wid >> 1, wn = wid & 1;

    const __half* Ag = g_Ah + (size_t)bm * KP;
    const __half* Bg = g_Bh + (size_t)bn * KP;

    float acc[2][8][4];
#pragma unroll
    for (int mt = 0; mt < 2; mt++)
#pragma unroll
        for (int nt = 0; nt < 8; nt++)
#pragma unroll
            for (int j = 0; j < 4; j++) acc[mt][nt][j] = 0.f;

    int a_row = wm * 32 + (lane & 7) + ((lane >> 3) & 1) * 8;   // + mt*16
    int a_ch  = (lane >> 4);                                     // + ks*2
    int b_row = wn * 64 + (lane & 7) + ((lane >> 4) & 1) * 8;   // + ntp*16
    int b_ch  = (lane >> 3) & 1;                                 // + ks*2

    load_tile(sb, Ag, Bg, t);
    load_tile(sb + STG, Ag + BK, Bg + BK, t);

    for (int kt = 0; kt < NK; kt++) {
        if (kt + 1 < NK)
            asm volatile("cp.async.wait_group 1;" ::: "memory");
        else
            asm volatile("cp.async.wait_group 0;" ::: "memory");
        __syncthreads();
        if (kt + 2 < NK)
            load_tile(sb + ((kt + 2) % NSTAGE) * STG,
                      Ag + (size_t)(kt + 2) * BK, Bg + (size_t)(kt + 2) * BK, t);

        uint32_t base = sb + (kt % NSTAGE) * STG;
#pragma unroll
        for (int ks = 0; ks < 4; ks++) {
            uint32_t af[2][4];
#pragma unroll
            for (int mt = 0; mt < 2; mt++) {
                int r = a_row + mt * 16;
                uint32_t ad = base + r * 128 + (((ks * 2 + a_ch) ^ (r & 7)) << 4);
                asm volatile("ldmatrix.sync.aligned.m8n8.x4.shared.b16 {%0,%1,%2,%3}, [%4];"
                             : "=r"(af[mt][0]), "=r"(af[mt][1]), "=r"(af[mt][2]), "=r"(af[mt][3])
                             : "r"(ad));
            }
            uint32_t bf[8][2];
#pragma unroll
            for (int ntp = 0; ntp < 4; ntp++) {
                int r = b_row + ntp * 16;
                uint32_t ad = base + 16384 + r * 128 + (((ks * 2 + b_ch) ^ (r & 7)) << 4);
                asm volatile("ldmatrix.sync.aligned.m8n8.x4.shared.b16 {%0,%1,%2,%3}, [%4];"
                             : "=r"(bf[ntp * 2][0]), "=r"(bf[ntp * 2][1]),
                               "=r"(bf[ntp * 2 + 1][0]), "=r"(bf[ntp * 2 + 1][1])
                             : "r"(ad));
            }
#pragma unroll
            for (int mt = 0; mt < 2; mt++)
#pragma unroll
                for (int nt = 0; nt < 8; nt++) {
                    asm volatile(
                        "mma.sync.aligned.m16n8k16.row.col.f32.f16.f16.f32 "
                        "{%0,%1,%2,%3}, {%4,%5,%6,%7}, {%8,%9}, {%0,%1,%2,%3};"
                        : "+f"(acc[mt][nt][0]), "+f"(acc[mt][nt][1]),
                          "+f"(acc[mt][nt][2]), "+f"(acc[mt][nt][3])
                        : "r"(af[mt][0]), "r"(af[mt][1]), "r"(af[mt][2]), "r"(af[mt][3]),
                          "r"(bf[nt][0]), "r"(bf[nt][1]));
                }
        }
    }

    // epilogue: fp16 stores + bias
#pragma unroll
    for (int mt = 0; mt < 2; mt++)
#pragma unroll
        for (int h2 = 0; h2 < 2; h2++) {
            int row = bm + wm * 32 + mt * 16 + (lane >> 2) + h2 * 8;
#pragma unroll
            for (int nt = 0; nt < 8; nt++) {
                int col = bn + wn * 64 + nt * 8 + (lane & 3) * 2;
                __half2 o = __floats2half2_rn(acc[mt][nt][h2 * 2 + 0] + g_bcat[col + 0],
                                              acc[mt][nt][h2 * 2 + 1] + g_bcat[col + 1]);
                *(__half2*)&g_qkvh[(size_t)row * GN + col] = o;
            }
        }
}

// ---------------- K2: pre = (mask ? log(max(relu(PE@Wpos^T+bpos),1e-6)) : -9e15) + lbias ----
__global__ __launch_bounds__(128)
void pos_kernel(const float* __restrict__ PEmb, const float* __restrict__ Wpos,
                const float* __restrict__ bpos, const int* __restrict__ adj,
                const float* __restrict__ lbias) {
    __shared__ float pe[128 * 65];
    __shared__ float wpT[64 * 17];
    __shared__ float bp[16];
    int t = threadIdx.x;
    size_t base = (size_t)blockIdx.x * 128 * 64;
    for (int i = t; i < 128 * 64; i += 128)
        pe[(i >> 6) * 65 + (i & 63)] = PEmb[base + i];
    for (int i = t; i < 1024; i += 128)
        wpT[(i & 63) * 17 + (i >> 6)] = Wpos[i];
    if (t < 16) bp[t] = bpos[t];
    __syncthreads();

    float s[16];
#pragma unroll
    for (int h = 0; h < 16; h++) s[h] = 0.f;
    const float* pr = &pe[t * 65];
#pragma unroll 8
    for (int p = 0; p < 64; p++) {
        float a = pr[p];
        const float* w = &wpT[p * 17];
#pragma unroll
        for (int h = 0; h < 16; h++) s[h] += a * w[h];
    }
    int r = blockIdx.x * 128 + t;     // r = (b*36+n)*36 + m
    int bn = r / 36, m = r % 36;
    bool live = adj[r] > 0;
    float lb = lbias[r];
    size_t ob = (size_t)bn * 16 * 36 + m;
#pragma unroll
    for (int h = 0; h < 16; h++) {
        float v = fmaxf(s[h] + bp[h], 1e-6f);
        g_pre[ob + (size_t)h * 36] = (live ? __logf(v) : -9e15f) + lb;
    }
}

// ---------------- K3: attention per (b,h), b-chunked ----------------
__global__ __launch_bounds__(256, 4)
void attn_kernel(const float* __restrict__ bout, float* __restrict__ out, int b_off) {
    __shared__ float qh[36][68];
    __shared__ float khT[64][40];
    __shared__ float vp[36][68];
    __shared__ float att[36 * 36];
    int b = b_off + (blockIdx.x >> 4), h = blockIdx.x & 15;
    int t = threadIdx.x;

    const __half* base = g_qkvh + (size_t)b * 36 * GN + h * 64;
    for (int i = t; i < 576; i += 256) {
        int n = i >> 4, c = (i & 15) << 2;
        const __half* rp = base + (size_t)n * GN + c;
        float2 q01 = __half22float2(*(const __half2*)rp);
        float2 q23 = __half22float2(*(const __half2*)(rp + 2));
        float2 k01 = __half22float2(*(const __half2*)(rp + 1024));
        float2 k23 = __half22float2(*(const __half2*)(rp + 1026));
        float2 v01 = __half22float2(*(const __half2*)(rp + 2048));
        float2 v23 = __half22float2(*(const __half2*)(rp + 2050));
        qh[n][c + 0] = q01.x; qh[n][c + 1] = q01.y;
        qh[n][c + 2] = q23.x; qh[n][c + 3] = q23.y;
        khT[c + 0][n] = k01.x; khT[c + 1][n] = k01.y;
        khT[c + 2][n] = k23.x; khT[c + 3][n] = k23.y;
        vp[n][c + 0] = v01.x; vp[n][c + 1] = v01.y;
        vp[n][c + 2] = v23.x; vp[n][c + 3] = v23.y;
    }
    __syncthreads();

    // logits: 2n x 4m register tile, 162 active threads; logit = q.k/8 + pre
    const float* pl = g_pre + (size_t)b * 36 * 576 + h * 36;
    if (t < 162) {
        int n0 = (t / 9) * 2, m0 = (t % 9) * 4;
        float4 s0 = make_float4(0.f, 0.f, 0.f, 0.f);
        float4 s1 = make_float4(0.f, 0.f, 0.f, 0.f);
#pragma unroll 8
        for (int d = 0; d < 64; d++) {
            float a0 = qh[n0][d], a1 = qh[n0 + 1][d];
            float4 kv = *(const float4*)&khT[d][m0];
            s0.x += a0 * kv.x; s0.y += a0 * kv.y; s0.z += a0 * kv.z; s0.w += a0 * kv.w;
            s1.x += a1 * kv.x; s1.y += a1 * kv.y; s1.z += a1 * kv.z; s1.w += a1 * kv.w;
        }
        const float* p0 = pl + (size_t)n0 * 576 + m0;
        const float* p1 = p0 + 576;
        att[n0 * 36 + m0 + 0] = s0.x * 0.125f + p0[0];
        att[n0 * 36 + m0 + 1] = s0.y * 0.125f + p0[1];
        att[n0 * 36 + m0 + 2] = s0.z * 0.125f + p0[2];
        att[n0 * 36 + m0 + 3] = s0.w * 0.125f + p0[3];
        att[(n0 + 1) * 36 + m0 + 0] = s1.x * 0.125f + p1[0];
        att[(n0 + 1) * 36 + m0 + 1] = s1.y * 0.125f + p1[1];
        att[(n0 + 1) * 36 + m0 + 2] = s1.z * 0.125f + p1[2];
        att[(n0 + 1) * 36 + m0 + 3] = s1.w * 0.125f + p1[3];
    }
    __syncthreads();

    // softmax over 36 (one warp per row)
    int warp = t >> 5, lane = t & 31;
    for (int n = warp; n < 36; n += 8) {
        float x1 = att[n * 36 + lane];
        float x2 = (lane < 4) ? att[n * 36 + 32 + lane] : -3e38f;
        float mx = fmaxf(x1, x2);
#pragma unroll
        for (int off = 16; off > 0; off >>= 1)
            mx = fmaxf(mx, __shfl_xor_sync(0xffffffffu, mx, off));
        float e1 = __expf(x1 - mx);
        float e2 = (lane < 4) ? __expf(x2 - mx) : 0.f;
        float sum = e1 + e2;
#pragma unroll
        for (int off = 16; off > 0; off >>= 1)
            sum += __shfl_xor_sync(0xffffffffu, sum, off);
        float inv = 1.f / sum;
        att[n * 36 + lane] = e1 * inv;
        if (lane < 4) att[n * 36 + 32 + lane] = e2 * inv;
    }
    __syncthreads();

    // out = att @ vp + bout : 2n x 8e register tile, 144 active threads
    const float* bo = bout + h * 64;
    if (t < 144) {
        int n0 = (t / 8) * 2, e0 = (t % 8) * 8;
        float4 a0a = *(const float4*)&bo[e0];
        float4 a0b = *(const float4*)&bo[e0 + 4];
        float4 a1a = a0a, a1b = a0b;
#pragma unroll 6
        for (int m = 0; m < 36; m++) {
            float w0 = att[n0 * 36 + m], w1 = att[(n0 + 1) * 36 + m];
            float4 va = *(const float4*)&vp[m][e0];
            float4 vb = *(const float4*)&vp[m][e0 + 4];
            a0a.x += w0 * va.x; a0a.y += w0 * va.y; a0a.z += w0 * va.z; a0a.w += w0 * va.w;
            a0b.x += w0 * vb.x; a0b.y += w0 * vb.y; a0b.z += w0 * vb.z; a0b.w += w0 * vb.w;
            a1a.x += w1 * va.x; a1a.y += w1 * va.y; a1a.z += w1 * va.z; a1a.w += w1 * va.w;
            a1b.x += w1 * vb.x; a1b.y += w1 * vb.y; a1b.z += w1 * vb.z; a1b.w += w1 * vb.w;
        }
        float* o0 = &out[(size_t)(b * 36 + n0) * 1024 + h * 64 + e0];
        *(float4*)o0 = a0a; *(float4*)(o0 + 4) = a0b;
        float* o1 = o0 + 1024;
        *(float4*)o1 = a1a; *(float4*)(o1 + 4) = a1b;
    }
}

// ---------------- launch: chunk-pipelined DAG ----------------
extern "C" void kernel_launch(void* const* d_in, const int* in_sizes, int n_in,
                              void* d_out, int out_size) {
    const float* roi  = (const float*)d_in[0];
    const int*   adj  = (const int*)  d_in[1];
    const float* pe   = (const float*)d_in[2];
    const float* lb   = (const float*)d_in[3];
    const float* Wq   = (const float*)d_in[4];
    const float* bq   = (const float*)d_in[5];
    const float* Wk   = (const float*)d_in[6];
    const float* bk   = (const float*)d_in[7];
    const float* Wpos = (const float*)d_in[8];
    const float* bpos = (const float*)d_in[9];
    const float* Wout = (const float*)d_in[10];
    const float* bout = (const float*)d_in[11];
    float* out = (float*)d_out;

    static int inited = 0;
    static cudaStream_t s1, s2;
    static cudaEvent_t eFork, eW, ePos, eG0, eG1, eG2, eDone;
    if (!inited) {
        cudaFuncSetAttribute(gemm_hmma, cudaFuncAttributeMaxDynamicSharedMemorySize,
                             NSTAGE * STG);
        cudaStreamCreateWithFlags(&s1, cudaStreamNonBlocking);
        cudaStreamCreateWithFlags(&s2, cudaStreamNonBlocking);
        cudaEventCreateWithFlags(&eFork, cudaEventDisableTiming);
        cudaEventCreateWithFlags(&eW, cudaEventDisableTiming);
        cudaEventCreateWithFlags(&ePos, cudaEventDisableTiming);
        cudaEventCreateWithFlags(&eG0, cudaEventDisableTiming);
        cudaEventCreateWithFlags(&eG1, cudaEventDisableTiming);
        cudaEventCreateWithFlags(&eG2, cudaEventDisableTiming);
        cudaEventCreateWithFlags(&eDone, cudaEventDisableTiming);
        inited = 1;
    }

    // fork side streams
    cudaEventRecord(eFork, 0);
    cudaStreamWaitEvent(s1, eFork, 0);
    cudaStreamWaitEvent(s2, eFork, 0);

    // s1: weight conversion + bias pack (needed by gemm)
    conv_B<<<GN * GK / 4 / 256, 256, 0, s1>>>(Wq, Wk, Wout);
    fill_bcat<<<GN / 256, 256, 0, s1>>>(bq, bk);
    cudaEventRecord(eW, s1);

    // s2: pos MLP + mask/bias prefold (needed only by attn)
    pos_kernel<<<(4608 * 36) / 128, 128, 0, s2>>>(pe, Wpos, bpos, adj, lb);

    // main: A conversion, then gemm chunks
    conv_A<<<GM * GK / 4 / 256, 256>>>(roi);
    cudaStreamWaitEvent(0, eW, 0);

    dim3 gg(GN / BN, CHUNK_ROWS / BM);   // 24 x 9
    gemm_hmma<<<gg, 256, NSTAGE * STG>>>(0 * CHUNK_ROWS);
    cudaEventRecord(eG0, 0);
    gemm_hmma<<<gg, 256, NSTAGE * STG>>>(1 * CHUNK_ROWS);
    cudaEventRecord(eG1, 0);
    gemm_hmma<<<gg, 256, NSTAGE * STG>>>(2 * CHUNK_ROWS);
    cudaEventRecord(eG2, 0);
    gemm_hmma<<<gg, 256, NSTAGE * STG>>>(3 * CHUNK_ROWS);

    // s2: attn chunks 0-2 overlap gemm chunks 1-3 (pos already ordered on s2)
    cudaStreamWaitEvent(s2, eG0, 0);
    attn_kernel<<<32 * 16, 256, 0, s2>>>(bout, out, 0);
    cudaStreamWaitEvent(s2, eG1, 0);
    attn_kernel<<<32 * 16, 256, 0, s2>>>(bout, out, 32);
    cudaStreamWaitEvent(s2, eG2, 0);
    attn_kernel<<<32 * 16, 256, 0, s2>>>(bout, out, 64);
    cudaEventRecord(eDone, s2);

    // main: last attn chunk after gemm3 (in-order) + pos
    attn_kernel<<<32 * 16, 256>>>(bout, out, 96);
    // join side work back into the origin stream
    cudaStreamWaitEvent(0, eDone, 0);
}

// round 15
// speedup vs baseline: 1.0228x; 1.0228x over previous
#include <cuda_runtime.h>
#include <cuda_fp16.h>
#include <math.h>
#include <cstdint>

// B=128, N=NONGT=36, D=1024, H=16, DG=64, PE=64
#define GM 4608      // rows = B*N
#define GN 3072      // cols = 3*1024  [q|k|vproj]
#define GK 1024      // inner dim
#define KP 1024      // fp16 K (single term Ah @ Bh)
#define BM 128
#define BN 128
#define BK 64
#define NK (KP / BK)   // 16
#define STG 32768      // stage stride: A 16KB + B 16KB
#define NSTAGE 3

// ---------------- device scratch ----------------
__device__ __align__(16) __half g_Ah[(size_t)GM * KP];    // 9.4 MB
__device__ __align__(16) __half g_Bh[(size_t)GN * KP];    // 6.3 MB  [N,K] K-major
__device__ __align__(16) float g_bcat[GN];
__device__ __align__(16) __half g_qkvh[(size_t)GM * GN];  // 28.3 MB fp16 [q|k|vproj]
__device__ __align__(16) float g_pre[4608 * 16 * 36];     // 10.6 MB pre[b,n][h][m]

// ---------------- helpers ----------------
__device__ __forceinline__ uint32_t smem_u32(const void* p) {
    uint32_t a;
    asm("{ .reg .u64 t; cvta.to.shared.u64 t, %1; cvt.u32.u64 %0, t; }" : "=r"(a) : "l"(p));
    return a;
}
__device__ __forceinline__ void cp16(uint32_t d, const void* s) {
    asm volatile("cp.async.cg.shared.global [%0], [%1], 16;" :: "r"(d), "l"(s));
}

// ---------------- K0a: A fp32 -> fp16 ----------------
__global__ __launch_bounds__(256) void conv_A(const float* __restrict__ A) {
    int i = blockIdx.x * 256 + threadIdx.x;
    float4 v = ((const float4*)A)[i];
    __half2 h01 = __halves2half2(__float2half_rn(v.x), __float2half_rn(v.y));
    __half2 h23 = __halves2half2(__float2half_rn(v.z), __float2half_rn(v.w));
    size_t base = (size_t)i * 4;
    *(__half2*)&g_Ah[base] = h01; *(__half2*)&g_Ah[base + 2] = h23;
}

// ---------------- K0b: weights -> fp16 ----------------
__global__ __launch_bounds__(256) void conv_B(const float* __restrict__ Wq,
                                              const float* __restrict__ Wk,
                                              const float* __restrict__ Wout) {
    int i = blockIdx.x * 256 + threadIdx.x;
    int row = i >> 8;
    int c4 = (i & 255) << 2;
    const float* src = (row < 1024) ? (Wq + (size_t)row * 1024)
                     : (row < 2048) ? (Wk + (size_t)(row - 1024) * 1024)
                                    : (Wout + (size_t)(row - 2048) * 1024);
    float4 v = *(const float4*)(src + c4);
    __half2 h01 = __halves2half2(__float2half_rn(v.x), __float2half_rn(v.y));
    __half2 h23 = __halves2half2(__float2half_rn(v.z), __float2half_rn(v.w));
    size_t base = (size_t)row * KP + c4;
    *(__half2*)&g_Bh[base] = h01; *(__half2*)&g_Bh[base + 2] = h23;
}

__global__ void fill_bcat(const float* __restrict__ bq, const float* __restrict__ bk) {
    int n = blockIdx.x * 256 + threadIdx.x;
    float v = 0.f;
    if (n < 1024) v = bq[n];
    else if (n < 2048) v = bk[n - 1024];
    g_bcat[n] = v;
}

// ---------------- K1: HMMA GEMM  qkv = A @ B^T + bcat (fp16 out) ----------------
__device__ __forceinline__ void load_tile(uint32_t base, const __half* Ag, const __half* Bg, int t) {
#pragma unroll
    for (int i = 0; i < 4; i++) {
        int u = t + i * 256;
        int row = u >> 3, k = u & 7;
        uint32_t sw = row * 128 + ((k ^ (row & 7)) << 4);
        cp16(base + sw, (const char*)(Ag + (size_t)row * KP) + k * 16);
        cp16(base + 16384 + sw, (const char*)(Bg + (size_t)row * KP) + k * 16);
    }
    asm volatile("cp.async.commit_group;" ::: "memory");
}

__global__ __launch_bounds__(256, 2) void gemm_hmma() {
    extern __shared__ char smem[];
    uint32_t sb = smem_u32(smem);
    int t = threadIdx.x, lane = t & 31, wid = t >> 5;
    int bm = blockIdx.y * BM, bn = blockIdx.x * BN;
    int wm = wid >> 1, wn = wid & 1;

    const __half* Ag = g_Ah + (size_t)bm * KP;
    const __half* Bg = g_Bh + (size_t)bn * KP;

    float acc[2][8][4];
#pragma unroll
    for (int mt = 0; mt < 2; mt++)
#pragma unroll
        for (int nt = 0; nt < 8; nt++)
#pragma unroll
            for (int j = 0; j < 4; j++) acc[mt][nt][j] = 0.f;

    int a_row = wm * 32 + (lane & 7) + ((lane >> 3) & 1) * 8;   // + mt*16
    int a_ch  = (lane >> 4);                                     // + ks*2
    int b_row = wn * 64 + (lane & 7) + ((lane >> 4) & 1) * 8;   // + ntp*16
    int b_ch  = (lane >> 3) & 1;                                 // + ks*2

    load_tile(sb, Ag, Bg, t);
    load_tile(sb + STG, Ag + BK, Bg + BK, t);

    for (int kt = 0; kt < NK; kt++) {
        if (kt + 1 < NK)
            asm volatile("cp.async.wait_group 1;" ::: "memory");
        else
            asm volatile("cp.async.wait_group 0;" ::: "memory");
        __syncthreads();
        if (kt + 2 < NK)
            load_tile(sb + ((kt + 2) % NSTAGE) * STG,
                      Ag + (size_t)(kt + 2) * BK, Bg + (size_t)(kt + 2) * BK, t);

        uint32_t base = sb + (kt % NSTAGE) * STG;
#pragma unroll
        for (int ks = 0; ks < 4; ks++) {
            uint32_t af[2][4];
#pragma unroll
            for (int mt = 0; mt < 2; mt++) {
                int r = a_row + mt * 16;
                uint32_t ad = base + r * 128 + (((ks * 2 + a_ch) ^ (r & 7)) << 4);
                asm volatile("ldmatrix.sync.aligned.m8n8.x4.shared.b16 {%0,%1,%2,%3}, [%4];"
                             : "=r"(af[mt][0]), "=r"(af[mt][1]), "=r"(af[mt][2]), "=r"(af[mt][3])
                             : "r"(ad));
            }
            uint32_t bf[8][2];
#pragma unroll
            for (int ntp = 0; ntp < 4; ntp++) {
                int r = b_row + ntp * 16;
                uint32_t ad = base + 16384 + r * 128 + (((ks * 2 + b_ch) ^ (r & 7)) << 4);
                asm volatile("ldmatrix.sync.aligned.m8n8.x4.shared.b16 {%0,%1,%2,%3}, [%4];"
                             : "=r"(bf[ntp * 2][0]), "=r"(bf[ntp * 2][1]),
                               "=r"(bf[ntp * 2 + 1][0]), "=r"(bf[ntp * 2 + 1][1])
                             : "r"(ad));
            }
#pragma unroll
            for (int mt = 0; mt < 2; mt++)
#pragma unroll
                for (int nt = 0; nt < 8; nt++) {
                    asm volatile(
                        "mma.sync.aligned.m16n8k16.row.col.f32.f16.f16.f32 "
                        "{%0,%1,%2,%3}, {%4,%5,%6,%7}, {%8,%9}, {%0,%1,%2,%3};"
                        : "+f"(acc[mt][nt][0]), "+f"(acc[mt][nt][1]),
                          "+f"(acc[mt][nt][2]), "+f"(acc[mt][nt][3])
                        : "r"(af[mt][0]), "r"(af[mt][1]), "r"(af[mt][2]), "r"(af[mt][3]),
                          "r"(bf[nt][0]), "r"(bf[nt][1]));
                }
        }
    }

    // epilogue: fp16 stores + bias
#pragma unroll
    for (int mt = 0; mt < 2; mt++)
#pragma unroll
        for (int h2 = 0; h2 < 2; h2++) {
            int row = bm + wm * 32 + mt * 16 + (lane >> 2) + h2 * 8;
#pragma unroll
            for (int nt = 0; nt < 8; nt++) {
                int col = bn + wn * 64 + nt * 8 + (lane & 3) * 2;
                __half2 o = __floats2half2_rn(acc[mt][nt][h2 * 2 + 0] + g_bcat[col + 0],
                                              acc[mt][nt][h2 * 2 + 1] + g_bcat[col + 1]);
                *(__half2*)&g_qkvh[(size_t)row * GN + col] = o;
            }
        }
}

// ---------------- K2: pre = (mask ? log(max(relu(PE@Wpos^T+bpos),1e-6)) : -9e15) + lbias ----
__global__ __launch_bounds__(128)
void pos_kernel(const float* __restrict__ PEmb, const float* __restrict__ Wpos,
                const float* __restrict__ bpos, const int* __restrict__ adj,
                const float* __restrict__ lbias) {
    __shared__ float pe[128 * 65];
    __shared__ float wpT[64 * 17];
    __shared__ float bp[16];
    int t = threadIdx.x;
    size_t base = (size_t)blockIdx.x * 128 * 64;
    for (int i = t; i < 128 * 64; i += 128)
        pe[(i >> 6) * 65 + (i & 63)] = PEmb[base + i];
    for (int i = t; i < 1024; i += 128)
        wpT[(i & 63) * 17 + (i >> 6)] = Wpos[i];
    if (t < 16) bp[t] = bpos[t];
    __syncthreads();

    float s[16];
#pragma unroll
    for (int h = 0; h < 16; h++) s[h] = 0.f;
    const float* pr = &pe[t * 65];
#pragma unroll 8
    for (int p = 0; p < 64; p++) {
        float a = pr[p];
        const float* w = &wpT[p * 17];
#pragma unroll
        for (int h = 0; h < 16; h++) s[h] += a * w[h];
    }
    int r = blockIdx.x * 128 + t;     // r = (b*36+n)*36 + m
    int bn = r / 36, m = r % 36;
    bool live = adj[r] > 0;
    float lb = lbias[r];
    size_t ob = (size_t)bn * 16 * 36 + m;
#pragma unroll
    for (int h = 0; h < 16; h++) {
        float v = fmaxf(s[h] + bp[h], 1e-6f);
        g_pre[ob + (size_t)h * 36] = (live ? __logf(v) : -9e15f) + lb;
    }
}

// ---------------- K3: attention per (b,h), fp16 qkv reads ----------------
__global__ __launch_bounds__(256, 4)
void attn_kernel(const float* __restrict__ bout, float* __restrict__ out) {
    __shared__ float qh[36][68];
    __shared__ float khT[64][40];
    __shared__ float vp[36][68];
    __shared__ float att[36 * 36];
    int b = blockIdx.x >> 4, h = blockIdx.x & 15;
    int t = threadIdx.x;

    const __half* base = g_qkvh + (size_t)b * 36 * GN + h * 64;
    for (int i = t; i < 576; i += 256) {
        int n = i >> 4, c = (i & 15) << 2;
        const __half* rp = base + (size_t)n * GN + c;
        float2 q01 = __half22float2(*(const __half2*)rp);
        float2 q23 = __half22float2(*(const __half2*)(rp + 2));
        float2 k01 = __half22float2(*(const __half2*)(rp + 1024));
        float2 k23 = __half22float2(*(const __half2*)(rp + 1026));
        float2 v01 = __half22float2(*(const __half2*)(rp + 2048));
        float2 v23 = __half22float2(*(const __half2*)(rp + 2050));
        qh[n][c + 0] = q01.x; qh[n][c + 1] = q01.y;
        qh[n][c + 2] = q23.x; qh[n][c + 3] = q23.y;
        khT[c + 0][n] = k01.x; khT[c + 1][n] = k01.y;
        khT[c + 2][n] = k23.x; khT[c + 3][n] = k23.y;
        vp[n][c + 0] = v01.x; vp[n][c + 1] = v01.y;
        vp[n][c + 2] = v23.x; vp[n][c + 3] = v23.y;
    }
    __syncthreads();

    // logits: 2n x 4m register tile, 162 active threads; logit = q.k/8 + pre
    const float* pl = g_pre + (size_t)b * 36 * 576 + h * 36;
    if (t < 162) {
        int n0 = (t / 9) * 2, m0 = (t % 9) * 4;
        float4 s0 = make_float4(0.f, 0.f, 0.f, 0.f);
        float4 s1 = make_float4(0.f, 0.f, 0.f, 0.f);
#pragma unroll 8
        for (int d = 0; d < 64; d++) {
            float a0 = qh[n0][d], a1 = qh[n0 + 1][d];
            float4 kv = *(const float4*)&khT[d][m0];
            s0.x += a0 * kv.x; s0.y += a0 * kv.y; s0.z += a0 * kv.z; s0.w += a0 * kv.w;
            s1.x += a1 * kv.x; s1.y += a1 * kv.y; s1.z += a1 * kv.z; s1.w += a1 * kv.w;
        }
        const float* p0 = pl + (size_t)n0 * 576 + m0;
        const float* p1 = p0 + 576;
        att[n0 * 36 + m0 + 0] = s0.x * 0.125f + p0[0];
        att[n0 * 36 + m0 + 1] = s0.y * 0.125f + p0[1];
        att[n0 * 36 + m0 + 2] = s0.z * 0.125f + p0[2];
        att[n0 * 36 + m0 + 3] = s0.w * 0.125f + p0[3];
        att[(n0 + 1) * 36 + m0 + 0] = s1.x * 0.125f + p1[0];
        att[(n0 + 1) * 36 + m0 + 1] = s1.y * 0.125f + p1[1];
        att[(n0 + 1) * 36 + m0 + 2] = s1.z * 0.125f + p1[2];
        att[(n0 + 1) * 36 + m0 + 3] = s1.w * 0.125f + p1[3];
    }
    __syncthreads();

    // softmax over 36 (one warp per row)
    int warp = t >> 5, lane = t & 31;
    for (int n = warp; n < 36; n += 8) {
        float x1 = att[n * 36 + lane];
        float x2 = (lane < 4) ? att[n * 36 + 32 + lane] : -3e38f;
        float mx = fmaxf(x1, x2);
#pragma unroll
        for (int off = 16; off > 0; off >>= 1)
            mx = fmaxf(mx, __shfl_xor_sync(0xffffffffu, mx, off));
        float e1 = __expf(x1 - mx);
        float e2 = (lane < 4) ? __expf(x2 - mx) : 0.f;
        float sum = e1 + e2;
#pragma unroll
        for (int off = 16; off > 0; off >>= 1)
            sum += __shfl_xor_sync(0xffffffffu, sum, off);
        float inv = 1.f / sum;
        att[n * 36 + lane] = e1 * inv;
        if (lane < 4) att[n * 36 + 32 + lane] = e2 * inv;
    }
    __syncthreads();

    // out = att @ vp + bout : 2n x 8e register tile, 144 active threads
    const float* bo = bout + h * 64;
    if (t < 144) {
        int n0 = (t / 8) * 2, e0 = (t % 8) * 8;
        float4 a0a = *(const float4*)&bo[e0];
        float4 a0b = *(const float4*)&bo[e0 + 4];
        float4 a1a = a0a, a1b = a0b;
#pragma unroll 6
        for (int m = 0; m < 36; m++) {
            float w0 = att[n0 * 36 + m], w1 = att[(n0 + 1) * 36 + m];
            float4 va = *(const float4*)&vp[m][e0];
            float4 vb = *(const float4*)&vp[m][e0 + 4];
            a0a.x += w0 * va.x; a0a.y += w0 * va.y; a0a.z += w0 * va.z; a0a.w += w0 * va.w;
            a0b.x += w0 * vb.x; a0b.y += w0 * vb.y; a0b.z += w0 * vb.z; a0b.w += w0 * vb.w;
            a1a.x += w1 * va.x; a1a.y += w1 * va.y; a1a.z += w1 * va.z; a1a.w += w1 * va.w;
            a1b.x += w1 * vb.x; a1b.y += w1 * vb.y; a1b.z += w1 * vb.z; a1b.w += w1 * vb.w;
        }
        float* o0 = &out[(size_t)(b * 36 + n0) * 1024 + h * 64 + e0];
        *(float4*)o0 = a0a; *(float4*)(o0 + 4) = a0b;
        float* o1 = o0 + 1024;
        *(float4*)o1 = a1a; *(float4*)(o1 + 4) = a1b;
    }
}

// ---------------- launch: fork/join DAG over side streams ----------------
extern "C" void kernel_launch(void* const* d_in, const int* in_sizes, int n_in,
                              void* d_out, int out_size) {
    const float* roi  = (const float*)d_in[0];
    const int*   adj  = (const int*)  d_in[1];
    const float* pe   = (const float*)d_in[2];
    const float* lb   = (const float*)d_in[3];
    const float* Wq   = (const float*)d_in[4];
    const float* bq   = (const float*)d_in[5];
    const float* Wk   = (const float*)d_in[6];
    const float* bk   = (const float*)d_in[7];
    const float* Wpos = (const float*)d_in[8];
    const float* bpos = (const float*)d_in[9];
    const float* Wout = (const float*)d_in[10];
    const float* bout = (const float*)d_in[11];
    float* out = (float*)d_out;

    static int inited = 0;
    static cudaStream_t s1, s2;
    static cudaEvent_t eFork, eW, ePos;
    if (!inited) {
        cudaFuncSetAttribute(gemm_hmma, cudaFuncAttributeMaxDynamicSharedMemorySize,
                             NSTAGE * STG);
        cudaStreamCreateWithFlags(&s1, cudaStreamNonBlocking);
        cudaStreamCreateWithFlags(&s2, cudaStreamNonBlocking);
        cudaEventCreateWithFlags(&eFork, cudaEventDisableTiming);
        cudaEventCreateWithFlags(&eW, cudaEventDisableTiming);
        cudaEventCreateWithFlags(&ePos, cudaEventDisableTiming);
        inited = 1;
    }

    // fork side streams off the (captured) legacy stream
    cudaEventRecord(eFork, 0);
    cudaStreamWaitEvent(s1, eFork, 0);
    cudaStreamWaitEvent(s2, eFork, 0);

    // s1: weight conversion + bias pack (needed by gemm)
    conv_B<<<GN * GK / 4 / 256, 256, 0, s1>>>(Wq, Wk, Wout);
    fill_bcat<<<GN / 256, 256, 0, s1>>>(bq, bk);
    cudaEventRecord(eW, s1);

    // s2: pos MLP + mask/bias prefold (needed only by attn) — overlaps conv_A + gemm
    pos_kernel<<<(4608 * 36) / 128, 128, 0, s2>>>(pe, Wpos, bpos, adj, lb);
    cudaEventRecord(ePos, s2);

    // main stream: A conversion, then gemm (after weights ready)
    conv_A<<<GM * GK / 4 / 256, 256>>>(roi);
    cudaStreamWaitEvent(0, eW, 0);

    dim3 gg(GN / BN, GM / BM);
    gemm_hmma<<<gg, 256, NSTAGE * STG>>>();

    // attn after gemm (stream order) and pos (event)
    cudaStreamWaitEvent(0, ePos, 0);
    attn_kernel<<<128 * 16, 256>>>(bout, out);
}

// round 16
// speedup vs baseline: 1.0585x; 1.0349x over previous
#include <cuda_runtime.h>
#include <cuda_fp16.h>
#include <math.h>
#include <cstdint>

// B=128, N=NONGT=36, D=1024, H=16, DG=64, PE=64
#define GM 4608      // rows = B*N
#define GN 3072      // cols = 3*1024  [q|k|vproj]
#define GK 1024      // inner dim
#define KP 1024      // fp16 K (single term Ah @ Bh)
#define BM 128
#define BN 128
#define BK 64
#define NK (KP / BK)   // 16
#define STG 32768      // stage stride: A 16KB + B 16KB
#define NSTAGE 3
#define CHUNK_ROWS 2304   // 18 block-rows = 64 batches per chunk (432 blocks > 1 wave)

// ---------------- device scratch ----------------
__device__ __align__(16) __half g_Ah[(size_t)GM * KP];    // 9.4 MB
__device__ __align__(16) __half g_Bh[(size_t)GN * KP];    // 6.3 MB  [N,K] K-major
__device__ __align__(16) float g_bcat[GN];
__device__ __align__(16) __half g_qkvh[(size_t)GM * GN];  // 28.3 MB fp16 [q|k|vproj]
__device__ __align__(16) float g_pre[4608 * 16 * 36];     // 10.6 MB pre[b,n][h][m]

// ---------------- helpers ----------------
__device__ __forceinline__ uint32_t smem_u32(const void* p) {
    uint32_t a;
    asm("{ .reg .u64 t; cvta.to.shared.u64 t, %1; cvt.u32.u64 %0, t; }" : "=r"(a) : "l"(p));
    return a;
}
__device__ __forceinline__ void cp16(uint32_t d, const void* s) {
    asm volatile("cp.async.cg.shared.global [%0], [%1], 16;" :: "r"(d), "l"(s));
}

// ---------------- K0a: A fp32 -> fp16 ----------------
__global__ __launch_bounds__(256) void conv_A(const float* __restrict__ A) {
    int i = blockIdx.x * 256 + threadIdx.x;
    float4 v = ((const float4*)A)[i];
    __half2 h01 = __halves2half2(__float2half_rn(v.x), __float2half_rn(v.y));
    __half2 h23 = __halves2half2(__float2half_rn(v.z), __float2half_rn(v.w));
    size_t base = (size_t)i * 4;
    *(__half2*)&g_Ah[base] = h01; *(__half2*)&g_Ah[base + 2] = h23;
}

// ---------------- K0b: weights -> fp16 ----------------
__global__ __launch_bounds__(256) void conv_B(const float* __restrict__ Wq,
                                              const float* __restrict__ Wk,
                                              const float* __restrict__ Wout) {
    int i = blockIdx.x * 256 + threadIdx.x;
    int row = i >> 8;
    int c4 = (i & 255) << 2;
    const float* src = (row < 1024) ? (Wq + (size_t)row * 1024)
                     : (row < 2048) ? (Wk + (size_t)(row - 1024) * 1024)
                                    : (Wout + (size_t)(row - 2048) * 1024);
    float4 v = *(const float4*)(src + c4);
    __half2 h01 = __halves2half2(__float2half_rn(v.x), __float2half_rn(v.y));
    __half2 h23 = __halves2half2(__float2half_rn(v.z), __float2half_rn(v.w));
    size_t base = (size_t)row * KP + c4;
    *(__half2*)&g_Bh[base] = h01; *(__half2*)&g_Bh[base + 2] = h23;
}

__global__ void fill_bcat(const float* __restrict__ bq, const float* __restrict__ bk) {
    int n = blockIdx.x * 256 + threadIdx.x;
    float v = 0.f;
    if (n < 1024) v = bq[n];
    else if (n < 2048) v = bk[n - 1024];
    g_bcat[n] = v;
}

// ---------------- K1: HMMA GEMM chunk  qkv[bm_off..] = A @ B^T + bcat (fp16 out) ----------------
__device__ __forceinline__ void load_tile(uint32_t base, const __half* Ag, const __half* Bg, int t) {
#pragma unroll
    for (int i = 0; i < 4; i++) {
        int u = t + i * 256;
        int row = u >> 3, k = u & 7;
        uint32_t sw = row * 128 + ((k ^ (row & 7)) << 4);
        cp16(base + sw, (const char*)(Ag + (size_t)row * KP) + k * 16);
        cp16(base + 16384 + sw, (const char*)(Bg + (size_t)row * KP) + k * 16);
    }
    asm volatile("cp.async.commit_group;" ::: "memory");
}

__global__ __launch_bounds__(256, 2) void gemm_hmma(int bm_off) {
    extern __shared__ char smem[];
    uint32_t sb = smem_u32(smem);
    int t = threadIdx.x, lane = t & 31, wid = t >> 5;
    int bm = bm_off + blockIdx.y * BM, bn = blockIdx.x * BN;
    int wm = wid >> 1, wn = wid & 1;

    const __half* Ag = g_Ah + (size_t)bm * KP;
    const __half* Bg = g_Bh + (size_t)bn * KP;

    float acc[2][8][4];
#pragma unroll
    for (int mt = 0; mt < 2; mt++)
#pragma unroll
        for (int nt = 0; nt < 8; nt++)
#pragma unroll
            for (int j = 0; j < 4; j++) acc[mt][nt][j] = 0.f;

    int a_row = wm * 32 + (lane & 7) + ((lane >> 3) & 1) * 8;   // + mt*16
    int a_ch  = (lane >> 4);                                     // + ks*2
    int b_row = wn * 64 + (lane & 7) + ((lane >> 4) & 1) * 8;   // + ntp*16
    int b_ch  = (lane >> 3) & 1;                                 // + ks*2

    load_tile(sb, Ag, Bg, t);
    load_tile(sb + STG, Ag + BK, Bg + BK, t);

    for (int kt = 0; kt < NK; kt++) {
        if (kt + 1 < NK)
            asm volatile("cp.async.wait_group 1;" ::: "memory");
        else
            asm volatile("cp.async.wait_group 0;" ::: "memory");
        __syncthreads();
        if (kt + 2 < NK)
            load_tile(sb + ((kt + 2) % NSTAGE) * STG,
                      Ag + (size_t)(kt + 2) * BK, Bg + (size_t)(kt + 2) * BK, t);

        uint32_t base = sb + (kt % NSTAGE) * STG;
#pragma unroll
        for (int ks = 0; ks < 4; ks++) {
            uint32_t af[2][4];
#pragma unroll
            for (int mt = 0; mt < 2; mt++) {
                int r = a_row + mt * 16;
                uint32_t ad = base + r * 128 + (((ks * 2 + a_ch) ^ (r & 7)) << 4);
                asm volatile("ldmatrix.sync.aligned.m8n8.x4.shared.b16 {%0,%1,%2,%3}, [%4];"
                             : "=r"(af[mt][0]), "=r"(af[mt][1]), "=r"(af[mt][2]), "=r"(af[mt][3])
                             : "r"(ad));
            }
            uint32_t bf[8][2];
#pragma unroll
            for (int ntp = 0; ntp < 4; ntp++) {
                int r = b_row + ntp * 16;
                uint32_t ad = base + 16384 + r * 128 + (((ks * 2 + b_ch) ^ (r & 7)) << 4);
                asm volatile("ldmatrix.sync.aligned.m8n8.x4.shared.b16 {%0,%1,%2,%3}, [%4];"
                             : "=r"(bf[ntp * 2][0]), "=r"(bf[ntp * 2][1]),
                               "=r"(bf[ntp * 2 + 1][0]), "=r"(bf[ntp * 2 + 1][1])
                             : "r"(ad));
            }
#pragma unroll
            for (int mt = 0; mt < 2; mt++)
#pragma unroll
                for (int nt = 0; nt < 8; nt++) {
                    asm volatile(
                        "mma.sync.aligned.m16n8k16.row.col.f32.f16.f16.f32 "
                        "{%0,%1,%2,%3}, {%4,%5,%6,%7}, {%8,%9}, {%0,%1,%2,%3};"
                        : "+f"(acc[mt][nt][0]), "+f"(acc[mt][nt][1]),
                          "+f"(acc[mt][nt][2]), "+f"(acc[mt][nt][3])
                        : "r"(af[mt][0]), "r"(af[mt][1]), "r"(af[mt][2]), "r"(af[mt][3]),
                          "r"(bf[nt][0]), "r"(bf[nt][1]));
                }
        }
    }

    // epilogue: fp16 stores + bias
#pragma unroll
    for (int mt = 0; mt < 2; mt++)
#pragma unroll
        for (int h2 = 0; h2 < 2; h2++) {
            int row = bm + wm * 32 + mt * 16 + (lane >> 2) + h2 * 8;
#pragma unroll
            for (int nt = 0; nt < 8; nt++) {
                int col = bn + wn * 64 + nt * 8 + (lane & 3) * 2;
                __half2 o = __floats2half2_rn(acc[mt][nt][h2 * 2 + 0] + g_bcat[col + 0],
                                              acc[mt][nt][h2 * 2 + 1] + g_bcat[col + 1]);
                *(__half2*)&g_qkvh[(size_t)row * GN + col] = o;
            }
        }
}

// ---------------- K2: pre = (mask ? log(max(relu(PE@Wpos^T+bpos),1e-6)) : -9e15) + lbias ----
__global__ __launch_bounds__(128)
void pos_kernel(const float* __restrict__ PEmb, const float* __restrict__ Wpos,
                const float* __restrict__ bpos, const int* __restrict__ adj,
                const float* __restrict__ lbias) {
    __shared__ float pe[128 * 65];
    __shared__ float wpT[64 * 17];
    __shared__ float bp[16];
    int t = threadIdx.x;
    size_t base = (size_t)blockIdx.x * 128 * 64;
    for (int i = t; i < 128 * 64; i += 128)
        pe[(i >> 6) * 65 + (i & 63)] = PEmb[base + i];
    for (int i = t; i < 1024; i += 128)
        wpT[(i & 63) * 17 + (i >> 6)] = Wpos[i];
    if (t < 16) bp[t] = bpos[t];
    __syncthreads();

    float s[16];
#pragma unroll
    for (int h = 0; h < 16; h++) s[h] = 0.f;
    const float* pr = &pe[t * 65];
#pragma unroll 8
    for (int p = 0; p < 64; p++) {
        float a = pr[p];
        const float* w = &wpT[p * 17];
#pragma unroll
        for (int h = 0; h < 16; h++) s[h] += a * w[h];
    }
    int r = blockIdx.x * 128 + t;     // r = (b*36+n)*36 + m
    int bn = r / 36, m = r % 36;
    bool live = adj[r] > 0;
    float lb = lbias[r];
    size_t ob = (size_t)bn * 16 * 36 + m;
#pragma unroll
    for (int h = 0; h < 16; h++) {
        float v = fmaxf(s[h] + bp[h], 1e-6f);
        g_pre[ob + (size_t)h * 36] = (live ? __logf(v) : -9e15f) + lb;
    }
}

// ---------------- K3: attention per (b,h), fp16 qkv reads, b-chunked ----------------
__global__ __launch_bounds__(256, 4)
void attn_kernel(const float* __restrict__ bout, float* __restrict__ out, int b_off) {
    __shared__ float qh[36][68];
    __shared__ float khT[64][40];
    __shared__ float vp[36][68];
    __shared__ float att[36 * 36];
    int b = b_off + (blockIdx.x >> 4), h = blockIdx.x & 15;
    int t = threadIdx.x;

    const __half* base = g_qkvh + (size_t)b * 36 * GN + h * 64;
    // q and v: coalesced row-major mapping
    for (int i = t; i < 576; i += 256) {
        int n = i >> 4, c = (i & 15) << 2;
        const __half* rp = base + (size_t)n * GN + c;
        float2 q01 = __half22float2(*(const __half2*)rp);
        float2 q23 = __half22float2(*(const __half2*)(rp + 2));
        float2 v01 = __half22float2(*(const __half2*)(rp + 2048));
        float2 v23 = __half22float2(*(const __half2*)(rp + 2050));
        qh[n][c + 0] = q01.x; qh[n][c + 1] = q01.y;
        qh[n][c + 2] = q23.x; qh[n][c + 3] = q23.y;
        vp[n][c + 0] = v01.x; vp[n][c + 1] = v01.y;
        vp[n][c + 2] = v23.x; vp[n][c + 3] = v23.y;
    }
    // k: n-fast mapping — lanes span 32 consecutive n values, so the 4
    // transposed stores khT[c+j][n] hit distinct banks (was 16-way conflict
    // with the row-major mapping: c*40 ≡ 0 mod 32 for c%4==0, bank = n∈{0,1}).
    for (int i = t; i < 576; i += 256) {
        int n = i % 36, c = (i / 36) << 2;
        const __half* rp = base + (size_t)n * GN + 1024 + c;
        float2 k01 = __half22float2(*(const __half2*)rp);
        float2 k23 = __half22float2(*(const __half2*)(rp + 2));
        khT[c + 0][n] = k01.x; khT[c + 1][n] = k01.y;
        khT[c + 2][n] = k23.x; khT[c + 3][n] = k23.y;
    }
    __syncthreads();

    // logits: 2n x 4m register tile, 162 active threads; logit = q.k/8 + pre
    const float* pl = g_pre + (size_t)b * 36 * 576 + h * 36;
    if (t < 162) {
        int n0 = (t / 9) * 2, m0 = (t % 9) * 4;
        float4 s0 = make_float4(0.f, 0.f, 0.f, 0.f);
        float4 s1 = make_float4(0.f, 0.f, 0.f, 0.f);
#pragma unroll 8
        for (int d = 0; d < 64; d++) {
            float a0 = qh[n0][d], a1 = qh[n0 + 1][d];
            float4 kv = *(const float4*)&khT[d][m0];
            s0.x += a0 * kv.x; s0.y += a0 * kv.y; s0.z += a0 * kv.z; s0.w += a0 * kv.w;
            s1.x += a1 * kv.x; s1.y += a1 * kv.y; s1.z += a1 * kv.z; s1.w += a1 * kv.w;
        }
        const float* p0 = pl + (size_t)n0 * 576 + m0;
        const float* p1 = p0 + 576;
        att[n0 * 36 + m0 + 0] = s0.x * 0.125f + p0[0];
        att[n0 * 36 + m0 + 1] = s0.y * 0.125f + p0[1];
        att[n0 * 36 + m0 + 2] = s0.z * 0.125f + p0[2];
        att[n0 * 36 + m0 + 3] = s0.w * 0.125f + p0[3];
        att[(n0 + 1) * 36 + m0 + 0] = s1.x * 0.125f + p1[0];
        att[(n0 + 1) * 36 + m0 + 1] = s1.y * 0.125f + p1[1];
        att[(n0 + 1) * 36 + m0 + 2] = s1.z * 0.125f + p1[2];
        att[(n0 + 1) * 36 + m0 + 3] = s1.w * 0.125f + p1[3];
    }
    __syncthreads();

    // softmax over 36 (one warp per row)
    int warp = t >> 5, lane = t & 31;
    for (int n = warp; n < 36; n += 8) {
        float x1 = att[n * 36 + lane];
        float x2 = (lane < 4) ? att[n * 36 + 32 + lane] : -3e38f;
        float mx = fmaxf(x1, x2);
#pragma unroll
        for (int off = 16; off > 0; off >>= 1)
            mx = fmaxf(mx, __shfl_xor_sync(0xffffffffu, mx, off));
        float e1 = __expf(x1 - mx);
        float e2 = (lane < 4) ? __expf(x2 - mx) : 0.f;
        float sum = e1 + e2;
#pragma unroll
        for (int off = 16; off > 0; off >>= 1)
            sum += __shfl_xor_sync(0xffffffffu, sum, off);
        float inv = 1.f / sum;
        att[n * 36 + lane] = e1 * inv;
        if (lane < 4) att[n * 36 + 32 + lane] = e2 * inv;
    }
    __syncthreads();

    // out = att @ vp + bout : 2n x 8e register tile, 144 active threads
    const float* bo = bout + h * 64;
    if (t < 144) {
        int n0 = (t / 8) * 2, e0 = (t % 8) * 8;
        float4 a0a = *(const float4*)&bo[e0];
        float4 a0b = *(const float4*)&bo[e0 + 4];
        float4 a1a = a0a, a1b = a0b;
#pragma unroll 6
        for (int m = 0; m < 36; m++) {
            float w0 = att[n0 * 36 + m], w1 = att[(n0 + 1) * 36 + m];
            float4 va = *(const float4*)&vp[m][e0];
            float4 vb = *(const float4*)&vp[m][e0 + 4];
            a0a.x += w0 * va.x; a0a.y += w0 * va.y; a0a.z += w0 * va.z; a0a.w += w0 * va.w;
            a0b.x += w0 * vb.x; a0b.y += w0 * vb.y; a0b.z += w0 * vb.z; a0b.w += w0 * vb.w;
            a1a.x += w1 * va.x; a1a.y += w1 * va.y; a1a.z += w1 * va.z; a1a.w += w1 * va.w;
            a1b.x += w1 * vb.x; a1b.y += w1 * vb.y; a1b.z += w1 * vb.z; a1b.w += w1 * vb.w;
        }
        float* o0 = &out[(size_t)(b * 36 + n0) * 1024 + h * 64 + e0];
        *(float4*)o0 = a0a; *(float4*)(o0 + 4) = a0b;
        float* o1 = o0 + 1024;
        *(float4*)o1 = a1a; *(float4*)(o1 + 4) = a1b;
    }
}

// ---------------- launch: 2-chunk pipelined DAG ----------------
extern "C" void kernel_launch(void* const* d_in, const int* in_sizes, int n_in,
                              void* d_out, int out_size) {
    const float* roi  = (const float*)d_in[0];
    const int*   adj  = (const int*)  d_in[1];
    const float* pe   = (const float*)d_in[2];
    const float* lb   = (const float*)d_in[3];
    const float* Wq   = (const float*)d_in[4];
    const float* bq   = (const float*)d_in[5];
    const float* Wk   = (const float*)d_in[6];
    const float* bk   = (const float*)d_in[7];
    const float* Wpos = (const float*)d_in[8];
    const float* bpos = (const float*)d_in[9];
    const float* Wout = (const float*)d_in[10];
    const float* bout = (const float*)d_in[11];
    float* out = (float*)d_out;

    static int inited = 0;
    static cudaStream_t s1, s2;
    static cudaEvent_t eFork, eW, eG0, eA0;
    if (!inited) {
        cudaFuncSetAttribute(gemm_hmma, cudaFuncAttributeMaxDynamicSharedMemorySize,
                             NSTAGE * STG);
        cudaStreamCreateWithFlags(&s1, cudaStreamNonBlocking);
        cudaStreamCreateWithFlags(&s2, cudaStreamNonBlocking);
        cudaEventCreateWithFlags(&eFork, cudaEventDisableTiming);
        cudaEventCreateWithFlags(&eW, cudaEventDisableTiming);
        cudaEventCreateWithFlags(&eG0, cudaEventDisableTiming);
        cudaEventCreateWithFlags(&eA0, cudaEventDisableTiming);
        inited = 1;
    }

    // fork side streams off the (captured) legacy stream
    cudaEventRecord(eFork, 0);
    cudaStreamWaitEvent(s1, eFork, 0);
    cudaStreamWaitEvent(s2, eFork, 0);

    // s1: weight conversion + bias pack (needed by gemm)
    conv_B<<<GN * GK / 4 / 256, 256, 0, s1>>>(Wq, Wk, Wout);
    fill_bcat<<<GN / 256, 256, 0, s1>>>(bq, bk);
    cudaEventRecord(eW, s1);

    // s2: pos MLP + mask/bias prefold (needed only by attn) — overlaps conv_A + gemm
    pos_kernel<<<(4608 * 36) / 128, 128, 0, s2>>>(pe, Wpos, bpos, adj, lb);

    // main: A conversion, then gemm chunk 0 (batches 0..63)
    conv_A<<<GM * GK / 4 / 256, 256>>>(roi);
    cudaStreamWaitEvent(0, eW, 0);

    dim3 gg(GN / BN, CHUNK_ROWS / BM);   // 24 x 18 = 432 blocks
    gemm_hmma<<<gg, 256, NSTAGE * STG>>>(0);
    cudaEventRecord(eG0, 0);
    gemm_hmma<<<gg, 256, NSTAGE * STG>>>(CHUNK_ROWS);

    // s2: attn chunk 0 (b 0..63) overlaps gemm chunk 1 (pos ordered before on s2)
    cudaStreamWaitEvent(s2, eG0, 0);
    attn_kernel<<<64 * 16, 256, 0, s2>>>(bout, out, 0);
    cudaEventRecord(eA0, s2);

    // main: attn chunk 1 (b 64..127) after gemm chunk 1 (stream order)
    attn_kernel<<<64 * 16, 256>>>(bout, out, 64);
    cudaStreamWaitEvent(0, eA0, 0);
}

// round 17
// speedup vs baseline: 1.1376x; 1.0748x over previous
#include <cuda_runtime.h>
#include <cuda_fp16.h>
#include <math.h>
#include <cstdint>

// B=128, N=NONGT=36, D=1024, H=16, DG=64, PE=64
#define GM 4608      // rows = B*N
#define GN 3072      // cols = 3*1024  [q|k|vproj]
#define GK 1024      // inner dim
#define KP 1024      // fp16 K (single term Ah @ Bh)
#define BM 128
#define BN 128
#define BK 64
#define NK (KP / BK)   // 16
#define STG 32768      // stage stride: A 16KB + B 16KB
#define NSTAGE 3
#define CHUNK_ROWS 2304   // 18 block-rows = 64 batches per chunk

// ---------------- device scratch ----------------
__device__ __align__(16) __half g_Ah[(size_t)GM * KP];    // 9.4 MB
__device__ __align__(16) __half g_Bh[(size_t)GN * KP];    // 6.3 MB  [N,K] K-major
__device__ __align__(16) float g_bcat[GN];
__device__ __align__(16) __half g_qkvh[(size_t)GM * GN];  // 28.3 MB fp16 [q|k|vproj]
__device__ __align__(16) float g_pre[4608 * 16 * 36];     // 10.6 MB pre[b,n][h][m]

// ---------------- helpers ----------------
__device__ __forceinline__ uint32_t smem_u32(const void* p) {
    uint32_t a;
    asm("{ .reg .u64 t; cvta.to.shared.u64 t, %1; cvt.u32.u64 %0, t; }" : "=r"(a) : "l"(p));
    return a;
}
__device__ __forceinline__ void cp16(uint32_t d, const void* s) {
    asm volatile("cp.async.cg.shared.global [%0], [%1], 16;" :: "r"(d), "l"(s));
}

// ---------------- K0a: A fp32 -> fp16 (chunked) ----------------
__global__ __launch_bounds__(256) void conv_A(const float* __restrict__ A, int off4) {
    int i = off4 + blockIdx.x * 256 + threadIdx.x;
    float4 v = ((const float4*)A)[i];
    __half2 h01 = __halves2half2(__float2half_rn(v.x), __float2half_rn(v.y));
    __half2 h23 = __halves2half2(__float2half_rn(v.z), __float2half_rn(v.w));
    size_t base = (size_t)i * 4;
    *(__half2*)&g_Ah[base] = h01; *(__half2*)&g_Ah[base + 2] = h23;
}

// ---------------- K0b: weights -> fp16 ----------------
__global__ __launch_bounds__(256) void conv_B(const float* __restrict__ Wq,
                                              const float* __restrict__ Wk,
                                              const float* __restrict__ Wout) {
    int i = blockIdx.x * 256 + threadIdx.x;
    int row = i >> 8;
    int c4 = (i & 255) << 2;
    const float* src = (row < 1024) ? (Wq + (size_t)row * 1024)
                     : (row < 2048) ? (Wk + (size_t)(row - 1024) * 1024)
                                    : (Wout + (size_t)(row - 2048) * 1024);
    float4 v = *(const float4*)(src + c4);
    __half2 h01 = __halves2half2(__float2half_rn(v.x), __float2half_rn(v.y));
    __half2 h23 = __halves2half2(__float2half_rn(v.z), __float2half_rn(v.w));
    size_t base = (size_t)row * KP + c4;
    *(__half2*)&g_Bh[base] = h01; *(__half2*)&g_Bh[base + 2] = h23;
}

__global__ void fill_bcat(const float* __restrict__ bq, const float* __restrict__ bk) {
    int n = blockIdx.x * 256 + threadIdx.x;
    float v = 0.f;
    if (n < 1024) v = bq[n];
    else if (n < 2048) v = bk[n - 1024];
    g_bcat[n] = v;
}

// ---------------- K1: HMMA GEMM chunk ----------------
__device__ __forceinline__ void load_tile(uint32_t base, const __half* Ag, const __half* Bg, int t) {
#pragma unroll
    for (int i = 0; i < 4; i++) {
        int u = t + i * 256;
        int row = u >> 3, k = u & 7;
        uint32_t sw = row * 128 + ((k ^ (row & 7)) << 4);
        cp16(base + sw, (const char*)(Ag + (size_t)row * KP) + k * 16);
        cp16(base + 16384 + sw, (const char*)(Bg + (size_t)row * KP) + k * 16);
    }
    asm volatile("cp.async.commit_group;" ::: "memory");
}

__global__ __launch_bounds__(256, 2) void gemm_hmma(int bm_off) {
    extern __shared__ char smem[];
    uint32_t sb = smem_u32(smem);
    int t = threadIdx.x, lane = t & 31, wid = t >> 5;
    int bm = bm_off + blockIdx.y * BM, bn = blockIdx.x * BN;
    int wm = wid >> 1, wn = wid & 1;

    const __half* Ag = g_Ah + (size_t)bm * KP;
    const __half* Bg = g_Bh + (size_t)bn * KP;

    float acc[2][8][4];
#pragma unroll
    for (int mt = 0; mt < 2; mt++)
#pragma unroll
        for (int nt = 0; nt < 8; nt++)
#pragma unroll
            for (int j = 0; j < 4; j++) acc[mt][nt][j] = 0.f;

    int a_row = wm * 32 + (lane & 7) + ((lane >> 3) & 1) * 8;
    int a_ch  = (lane >> 4);
    int b_row = wn * 64 + (lane & 7) + ((lane >> 4) & 1) * 8;
    int b_ch  = (lane >> 3) & 1;

    load_tile(sb, Ag, Bg, t);
    load_tile(sb + STG, Ag + BK, Bg + BK, t);

    for (int kt = 0; kt < NK; kt++) {
        if (kt + 1 < NK)
            asm volatile("cp.async.wait_group 1;" ::: "memory");
        else
            asm volatile("cp.async.wait_group 0;" ::: "memory");
        __syncthreads();
        if (kt + 2 < NK)
            load_tile(sb + ((kt + 2) % NSTAGE) * STG,
                      Ag + (size_t)(kt + 2) * BK, Bg + (size_t)(kt + 2) * BK, t);

        uint32_t base = sb + (kt % NSTAGE) * STG;
#pragma unroll
        for (int ks = 0; ks < 4; ks++) {
            uint32_t af[2][4];
#pragma unroll
            for (int mt = 0; mt < 2; mt++) {
                int r = a_row + mt * 16;
                uint32_t ad = base + r * 128 + (((ks * 2 + a_ch) ^ (r & 7)) << 4);
                asm volatile("ldmatrix.sync.aligned.m8n8.x4.shared.b16 {%0,%1,%2,%3}, [%4];"
                             : "=r"(af[mt][0]), "=r"(af[mt][1]), "=r"(af[mt][2]), "=r"(af[mt][3])
                             : "r"(ad));
            }
            uint32_t bf[8][2];
#pragma unroll
            for (int ntp = 0; ntp < 4; ntp++) {
                int r = b_row + ntp * 16;
                uint32_t ad = base + 16384 + r * 128 + (((ks * 2 + b_ch) ^ (r & 7)) << 4);
                asm volatile("ldmatrix.sync.aligned.m8n8.x4.shared.b16 {%0,%1,%2,%3}, [%4];"
                             : "=r"(bf[ntp * 2][0]), "=r"(bf[ntp * 2][1]),
                               "=r"(bf[ntp * 2 + 1][0]), "=r"(bf[ntp * 2 + 1][1])
                             : "r"(ad));
            }
#pragma unroll
            for (int mt = 0; mt < 2; mt++)
#pragma unroll
                for (int nt = 0; nt < 8; nt++) {
                    asm volatile(
                        "mma.sync.aligned.m16n8k16.row.col.f32.f16.f16.f32 "
                        "{%0,%1,%2,%3}, {%4,%5,%6,%7}, {%8,%9}, {%0,%1,%2,%3};"
                        : "+f"(acc[mt][nt][0]), "+f"(acc[mt][nt][1]),
                          "+f"(acc[mt][nt][2]), "+f"(acc[mt][nt][3])
                        : "r"(af[mt][0]), "r"(af[mt][1]), "r"(af[mt][2]), "r"(af[mt][3]),
                          "r"(bf[nt][0]), "r"(bf[nt][1]));
                }
        }
    }

#pragma unroll
    for (int mt = 0; mt < 2; mt++)
#pragma unroll
        for (int h2 = 0; h2 < 2; h2++) {
            int row = bm + wm * 32 + mt * 16 + (lane >> 2) + h2 * 8;
#pragma unroll
            for (int nt = 0; nt < 8; nt++) {
                int col = bn + wn * 64 + nt * 8 + (lane & 3) * 2;
                __half2 o = __floats2half2_rn(acc[mt][nt][h2 * 2 + 0] + g_bcat[col + 0],
                                              acc[mt][nt][h2 * 2 + 1] + g_bcat[col + 1]);
                *(__half2*)&g_qkvh[(size_t)row * GN + col] = o;
            }
        }
}

// ---------------- K2: pre = (mask ? log(max(relu(PE@Wpos^T+bpos),1e-6)) : -9e15) + lbias ----
__global__ __launch_bounds__(128)
void pos_kernel(const float* __restrict__ PEmb, const float* __restrict__ Wpos,
                const float* __restrict__ bpos, const int* __restrict__ adj,
                const float* __restrict__ lbias) {
    __shared__ float pe[128 * 65];
    __shared__ float wpT[64 * 17];
    __shared__ float bp[16];
    int t = threadIdx.x;
    size_t base = (size_t)blockIdx.x * 128 * 64;
    for (int i = t; i < 128 * 64; i += 128)
        pe[(i >> 6) * 65 + (i & 63)] = PEmb[base + i];
    for (int i = t; i < 1024; i += 128)
        wpT[(i & 63) * 17 + (i >> 6)] = Wpos[i];
    if (t < 16) bp[t] = bpos[t];
    __syncthreads();

    float s[16];
#pragma unroll
    for (int h = 0; h < 16; h++) s[h] = 0.f;
    const float* pr = &pe[t * 65];
#pragma unroll 8
    for (int p = 0; p < 64; p++) {
        float a = pr[p];
        const float* w = &wpT[p * 17];
#pragma unroll
        for (int h = 0; h < 16; h++) s[h] += a * w[h];
    }
    int r = blockIdx.x * 128 + t;     // r = (b*36+n)*36 + m
    int bn = r / 36, m = r % 36;
    bool live = adj[r] > 0;
    float lb = lbias[r];
    size_t ob = (size_t)bn * 16 * 36 + m;
#pragma unroll
    for (int h = 0; h < 16; h++) {
        float v = fmaxf(s[h] + bp[h], 1e-6f);
        g_pre[ob + (size_t)h * 36] = (live ? __logf(v) : -9e15f) + lb;
    }
}

// ---------------- K3: attention per (b,h) — fp16 smem for k/v ----------------
__global__ __launch_bounds__(256, 4)
void attn_kernel(const float* __restrict__ bout, float* __restrict__ out, int b_off) {
    __shared__ float  qh[36][68];     // fp32 (broadcast loads, cheap)
    __shared__ __half khT[64][40];    // fp16: logits load 8 B/iter instead of 16
    __shared__ __half vp[36][72];     // fp16: av load 16 B/m instead of 32
    __shared__ float  att[36 * 36];
    int b = b_off + (blockIdx.x >> 4), h = blockIdx.x & 15;
    int t = threadIdx.x;

    const __half* base = g_qkvh + (size_t)b * 36 * GN + h * 64;
    // q (convert to fp32) and v (copy half2s) — row-major coalesced mapping
    for (int i = t; i < 576; i += 256) {
        int n = i >> 4, c = (i & 15) << 2;
        const __half* rp = base + (size_t)n * GN + c;
        __half2 q01 = *(const __half2*)rp;
        __half2 q23 = *(const __half2*)(rp + 2);
        float2 f01 = __half22float2(q01), f23 = __half22float2(q23);
        qh[n][c + 0] = f01.x; qh[n][c + 1] = f01.y;
        qh[n][c + 2] = f23.x; qh[n][c + 3] = f23.y;
        *(__half2*)&vp[n][c + 0] = *(const __half2*)(rp + 2048);
        *(__half2*)&vp[n][c + 2] = *(const __half2*)(rp + 2050);
    }
    // k transpose: pair-granularity (2 n, 2 c per unit) so smem stores are half2
    // over consecutive n — conflict-light. 18 n-pairs x 32 c-pairs = 576 units.
    for (int i = t; i < 576; i += 256) {
        int n2 = (i % 18) * 2, c2 = (i / 18) * 2;
        const __half* rp = base + (size_t)n2 * GN + 1024 + c2;
        __half2 va = *(const __half2*)rp;            // k[n2][c2], k[n2][c2+1]
        __half2 vb = *(const __half2*)(rp + GN);     // k[n2+1][c2], k[n2+1][c2+1]
        *(__half2*)&khT[c2 + 0][n2] = __halves2half2(__low2half(va), __low2half(vb));
        *(__half2*)&khT[c2 + 1][n2] = __halves2half2(__high2half(va), __high2half(vb));
    }
    __syncthreads();

    // logits: 2n x 4m register tile, 162 active threads; logit = q.k/8 + pre
    const float* pl = g_pre + (size_t)b * 36 * 576 + h * 36;
    if (t < 162) {
        int n0 = (t / 9) * 2, m0 = (t % 9) * 4;
        float4 s0 = make_float4(0.f, 0.f, 0.f, 0.f);
        float4 s1 = make_float4(0.f, 0.f, 0.f, 0.f);
#pragma unroll 8
        for (int d = 0; d < 64; d++) {
            float a0 = qh[n0][d], a1 = qh[n0 + 1][d];
            float2 kraw = *(const float2*)&khT[d][m0];      // 4 halves, one LDS.64
            float2 k01 = __half22float2(*(__half2*)&kraw.x);
            float2 k23 = __half22float2(*(__half2*)&kraw.y);
            s0.x += a0 * k01.x; s0.y += a0 * k01.y; s0.z += a0 * k23.x; s0.w += a0 * k23.y;
            s1.x += a1 * k01.x; s1.y += a1 * k01.y; s1.z += a1 * k23.x; s1.w += a1 * k23.y;
        }
        const float* p0 = pl + (size_t)n0 * 576 + m0;
        const float* p1 = p0 + 576;
        att[n0 * 36 + m0 + 0] = s0.x * 0.125f + p0[0];
        att[n0 * 36 + m0 + 1] = s0.y * 0.125f + p0[1];
        att[n0 * 36 + m0 + 2] = s0.z * 0.125f + p0[2];
        att[n0 * 36 + m0 + 3] = s0.w * 0.125f + p0[3];
        att[(n0 + 1) * 36 + m0 + 0] = s1.x * 0.125f + p1[0];
        att[(n0 + 1) * 36 + m0 + 1] = s1.y * 0.125f + p1[1];
        att[(n0 + 1) * 36 + m0 + 2] = s1.z * 0.125f + p1[2];
        att[(n0 + 1) * 36 + m0 + 3] = s1.w * 0.125f + p1[3];
    }
    __syncthreads();

    // softmax over 36 (one warp per row)
    int warp = t >> 5, lane = t & 31;
    for (int n = warp; n < 36; n += 8) {
        float x1 = att[n * 36 + lane];
        float x2 = (lane < 4) ? att[n * 36 + 32 + lane] : -3e38f;
        float mx = fmaxf(x1, x2);
#pragma unroll
        for (int off = 16; off > 0; off >>= 1)
            mx = fmaxf(mx, __shfl_xor_sync(0xffffffffu, mx, off));
        float e1 = __expf(x1 - mx);
        float e2 = (lane < 4) ? __expf(x2 - mx) : 0.f;
        float sum = e1 + e2;
#pragma unroll
        for (int off = 16; off > 0; off >>= 1)
            sum += __shfl_xor_sync(0xffffffffu, sum, off);
        float inv = 1.f / sum;
        att[n * 36 + lane] = e1 * inv;
        if (lane < 4) att[n * 36 + 32 + lane] = e2 * inv;
    }
    __syncthreads();

    // out = att @ vp + bout : 2n x 8e register tile, 144 active threads
    const float* bo = bout + h * 64;
    if (t < 144) {
        int n0 = (t / 8) * 2, e0 = (t % 8) * 8;
        float4 a0a = *(const float4*)&bo[e0];
        float4 a0b = *(const float4*)&bo[e0 + 4];
        float4 a1a = a0a, a1b = a0b;
#pragma unroll 6
        for (int m = 0; m < 36; m++) {
            float w0 = att[n0 * 36 + m], w1 = att[(n0 + 1) * 36 + m];
            uint4 raw = *(const uint4*)&vp[m][e0];    // 8 halves, one LDS.128
            float2 v01 = __half22float2(*(__half2*)&raw.x);
            float2 v23 = __half22float2(*(__half2*)&raw.y);
            float2 v45 = __half22float2(*(__half2*)&raw.z);
            float2 v67 = __half22float2(*(__half2*)&raw.w);
            a0a.x += w0 * v01.x; a0a.y += w0 * v01.y; a0a.z += w0 * v23.x; a0a.w += w0 * v23.y;
            a0b.x += w0 * v45.x; a0b.y += w0 * v45.y; a0b.z += w0 * v67.x; a0b.w += w0 * v67.y;
            a1a.x += w1 * v01.x; a1a.y += w1 * v01.y; a1a.z += w1 * v23.x; a1a.w += w1 * v23.y;
            a1b.x += w1 * v45.x; a1b.y += w1 * v45.y; a1b.z += w1 * v67.x; a1b.w += w1 * v67.y;
        }
        float* o0 = &out[(size_t)(b * 36 + n0) * 1024 + h * 64 + e0];
        *(float4*)o0 = a0a; *(float4*)(o0 + 4) = a0b;
        float* o1 = o0 + 1024;
        *(float4*)o1 = a1a; *(float4*)(o1 + 4) = a1b;
    }
}

// ---------------- launch: 2-chunk pipelined DAG ----------------
extern "C" void kernel_launch(void* const* d_in, const int* in_sizes, int n_in,
                              void* d_out, int out_size) {
    const float* roi  = (const float*)d_in[0];
    const int*   adj  = (const int*)  d_in[1];
    const float* pe   = (const float*)d_in[2];
    const float* lb   = (const float*)d_in[3];
    const float* Wq   = (const float*)d_in[4];
    const float* bq   = (const float*)d_in[5];
    const float* Wk   = (const float*)d_in[6];
    const float* bk   = (const float*)d_in[7];
    const float* Wpos = (const float*)d_in[8];
    const float* bpos = (const float*)d_in[9];
    const float* Wout = (const float*)d_in[10];
    const float* bout = (const float*)d_in[11];
    float* out = (float*)d_out;

    static int inited = 0;
    static cudaStream_t s1, s2;
    static cudaEvent_t eFork, eW, eA1, eG0, eA0;
    if (!inited) {
        cudaFuncSetAttribute(gemm_hmma, cudaFuncAttributeMaxDynamicSharedMemorySize,
                             NSTAGE * STG);
        cudaStreamCreateWithFlags(&s1, cudaStreamNonBlocking);
        cudaStreamCreateWithFlags(&s2, cudaStreamNonBlocking);
        cudaEventCreateWithFlags(&eFork, cudaEventDisableTiming);
        cudaEventCreateWithFlags(&eW, cudaEventDisableTiming);
        cudaEventCreateWithFlags(&eA1, cudaEventDisableTiming);
        cudaEventCreateWithFlags(&eG0, cudaEventDisableTiming);
        cudaEventCreateWithFlags(&eA0, cudaEventDisableTiming);
        inited = 1;
    }

    const int HALF4 = GM * GK / 4 / 2;   // float4 elements per A half

    // fork side streams off the (captured) legacy stream
    cudaEventRecord(eFork, 0);
    cudaStreamWaitEvent(s1, eFork, 0);
    cudaStreamWaitEvent(s2, eFork, 0);

    // s1: weight conversion + bias pack, then A chunk 1 conversion
    conv_B<<<GN * GK / 4 / 256, 256, 0, s1>>>(Wq, Wk, Wout);
    fill_bcat<<<GN / 256, 256, 0, s1>>>(bq, bk);
    cudaEventRecord(eW, s1);
    conv_A<<<HALF4 / 256, 256, 0, s1>>>(roi, HALF4);
    cudaEventRecord(eA1, s1);

    // s2: pos MLP + mask/bias prefold (needed only by attn)
    pos_kernel<<<(4608 * 36) / 128, 128, 0, s2>>>(pe, Wpos, bpos, adj, lb);

    // main: A chunk 0, then gemm chunk 0 (weights via eW)
    conv_A<<<HALF4 / 256, 256>>>(roi, 0);
    cudaStreamWaitEvent(0, eW, 0);

    dim3 gg(GN / BN, CHUNK_ROWS / BM);   // 24 x 18 = 432 blocks
    gemm_hmma<<<gg, 256, NSTAGE * STG>>>(0);
    cudaEventRecord(eG0, 0);
    cudaStreamWaitEvent(0, eA1, 0);
    gemm_hmma<<<gg, 256, NSTAGE * STG>>>(CHUNK_ROWS);

    // s2: attn chunk 0 (b 0..63) overlaps gemm chunk 1
    cudaStreamWaitEvent(s2, eG0, 0);
    attn_kernel<<<64 * 16, 256, 0, s2>>>(bout, out, 0);
    cudaEventRecord(eA0, s2);

    // main: attn chunk 1 (b 64..127) after gemm chunk 1
    attn_kernel<<<64 * 16, 256>>>(bout, out, 64);
    cudaStreamWaitEvent(0, eA0, 0);
}